// round 2
// baseline (speedup 1.0000x reference)
#include <cuda_runtime.h>
#include <cuda_bf16.h>

// out[b,t,c] = (x[b,src,c] + noise[b,src,c]*0.1f) * scale[b]
// src = (t - (shifts[b] - MAX_SHIFT)) mod T
// B=64, T=4096, C=128, fp32. Pure HBM-streaming; optimize achieved BW.

#define B_DIM 64
#define T_DIM 4096
#define C_DIM 128
#define MAX_SHIFT 409
#define NOISE_STD 0.1f

#define C4 (C_DIM / 4)      // 32 float4 per (b,t) row
#define ITEMS 4             // float4 per thread
#define THREADS 256

__global__ __launch_bounds__(THREADS)
void ts_augment_kernel(const float4* __restrict__ x,
                       const float4* __restrict__ noise,
                       const float*  __restrict__ scale,
                       const int*    __restrict__ shifts,
                       float4*       __restrict__ out)
{
    // Each block covers THREADS*ITEMS = 1024 contiguous float4 = 32 t-rows.
    // T_DIM*C4 = 131072 per batch, divisible by 1024 -> b constant per block.
    const unsigned base = blockIdx.x * (THREADS * ITEMS) + threadIdx.x;
    const unsigned b = base >> 17;                 // / (T_DIM*C4)

    const int s = shifts[b] - MAX_SHIFT;           // [-409, 409]
    const float sc = scale[b];
    const unsigned b_base = b << 17;

    unsigned src_idx[ITEMS];
    unsigned dst_idx[ITEMS];
    #pragma unroll
    for (int k = 0; k < ITEMS; k++) {
        unsigned idx = base + k * THREADS;
        unsigned c4 = idx & (C4 - 1);
        unsigned t  = (idx >> 5) & (T_DIM - 1);
        int src = (int)t - s;
        if (src < 0)           src += T_DIM;
        else if (src >= T_DIM) src -= T_DIM;
        src_idx[k] = b_base + ((unsigned)src << 5) + c4;
        dst_idx[k] = idx;
    }

    // Front-batch all 8 loads for maximum MLP; evict-first (touch-once data).
    float4 xv[ITEMS], nv[ITEMS];
    #pragma unroll
    for (int k = 0; k < ITEMS; k++) xv[k] = __ldcs(&x[src_idx[k]]);
    #pragma unroll
    for (int k = 0; k < ITEMS; k++) nv[k] = __ldcs(&noise[src_idx[k]]);

    #pragma unroll
    for (int k = 0; k < ITEMS; k++) {
        float4 o;
        o.x = fmaf(nv[k].x, NOISE_STD, xv[k].x) * sc;
        o.y = fmaf(nv[k].y, NOISE_STD, xv[k].y) * sc;
        o.z = fmaf(nv[k].z, NOISE_STD, xv[k].z) * sc;
        o.w = fmaf(nv[k].w, NOISE_STD, xv[k].w) * sc;
        __stcs(&out[dst_idx[k]], o);
    }
}

extern "C" void kernel_launch(void* const* d_in, const int* in_sizes, int n_in,
                              void* d_out, int out_size)
{
    const float4* x      = (const float4*)d_in[0];
    const float4* noise  = (const float4*)d_in[1];
    const float*  scale  = (const float*)d_in[2];
    const int*    shifts = (const int*)d_in[3];
    float4* out = (float4*)d_out;

    const unsigned total = B_DIM * T_DIM * C4;          // 8,388,608 float4
    const unsigned blocks = total / (THREADS * ITEMS);  // 8192

    ts_augment_kernel<<<blocks, THREADS>>>(x, noise, scale, shifts, out);
}

// round 3
// speedup vs baseline: 1.0385x; 1.0385x over previous
#include <cuda_runtime.h>
#include <cuda_bf16.h>

// out[b,t,c] = (x[b,src,c] + noise[b,src,c]*0.1f) * scale[b]
// src = (t - (shifts[b] - MAX_SHIFT)) mod T
// B=64, T=4096, C=128, fp32. HBM-streaming; R1 shape + streaming cache hints.

#define B_DIM 64
#define T_DIM 4096
#define C_DIM 128
#define MAX_SHIFT 409
#define NOISE_STD 0.1f

#define C4 (C_DIM / 4)   // 32 float4 per (b,t) row

__global__ __launch_bounds__(256)
void ts_augment_kernel(const float4* __restrict__ x,
                       const float4* __restrict__ noise,
                       const float*  __restrict__ scale,
                       const int*    __restrict__ shifts,
                       float4*       __restrict__ out)
{
    // flat index over B * T * C4 = 8,388,608; grid*block covers exactly.
    unsigned idx = blockIdx.x * blockDim.x + threadIdx.x;
    unsigned c4 = idx & (C4 - 1);            // idx % 32
    unsigned t  = (idx >> 5) & (T_DIM - 1);  // (idx / 32) % 4096
    unsigned b  = idx >> 17;                 // idx / (32*4096)

    int s = shifts[b] - MAX_SHIFT;           // [-409, 409]
    int src = (int)t - s;                    // [-409, 4504]
    if (src < 0)           src += T_DIM;
    else if (src >= T_DIM) src -= T_DIM;

    unsigned src_idx = (b << 17) + ((unsigned)src << 5) + c4;

    // Touch-once streams: evict-first reads, streaming store.
    float4 xv = __ldcs(&x[src_idx]);
    float4 nv = __ldcs(&noise[src_idx]);
    float sc = __ldg(&scale[b]);

    float4 o;
    o.x = fmaf(nv.x, NOISE_STD, xv.x) * sc;
    o.y = fmaf(nv.y, NOISE_STD, xv.y) * sc;
    o.z = fmaf(nv.z, NOISE_STD, xv.z) * sc;
    o.w = fmaf(nv.w, NOISE_STD, xv.w) * sc;

    __stcs(&out[idx], o);
}

extern "C" void kernel_launch(void* const* d_in, const int* in_sizes, int n_in,
                              void* d_out, int out_size)
{
    const float4* x      = (const float4*)d_in[0];
    const float4* noise  = (const float4*)d_in[1];
    const float*  scale  = (const float*)d_in[2];
    const int*    shifts = (const int*)d_in[3];
    float4* out = (float4*)d_out;

    const unsigned total = B_DIM * T_DIM * C4;   // 8,388,608
    const unsigned threads = 256;
    const unsigned blocks = total / threads;     // 32768

    ts_augment_kernel<<<blocks, threads>>>(x, noise, scale, shifts, out);
}